// round 14
// baseline (speedup 1.0000x reference)
#include <cuda_runtime.h>
#include <math.h>

#define BB 32
#define SS 1024
#define II 512
#define HH 512

typedef unsigned long long u64;

// ---------------- device scratch ----------------
__device__ float g_xt[(size_t)SS * 16384];   // x transposed: [t][kquad][b][4], 64MB
__device__ float g_hb[2][HH * BB];           // h ping-pong: [kquad][b][4]
__device__ unsigned g_bkt[16 * 4 * 32];      // 16 buckets x 4 replicated copies (128B apart)
__device__ unsigned g_end;                   // end-of-kernel cleanup counter

__device__ __forceinline__ unsigned ld_acq(const unsigned* p) {
    unsigned v;
    asm volatile("ld.acquire.gpu.u32 %0, [%1];" : "=r"(v) : "l"(p));
    return v;
}
__device__ __forceinline__ u64 fma2(u64 a, u64 b, u64 c) {
    u64 d;
    asm("fma.rn.f32x2 %0, %1, %2, %3;" : "=l"(d) : "l"(a), "l"(b), "l"(c));
    return d;
}
__device__ __forceinline__ u64 add2(u64 a, u64 b) {
    u64 d;
    asm("add.rn.f32x2 %0, %1, %2;" : "=l"(d) : "l"(a), "l"(b));
    return d;
}
__device__ __forceinline__ float2 unpack2(u64 v) {
    unsigned lo, hi;
    asm("mov.b64 {%0, %1}, %2;" : "=r"(lo), "=r"(hi) : "l"(v));
    return make_float2(__uint_as_float(lo), __uint_as_float(hi));
}
__device__ __forceinline__ ulonglong2 ldcg_v2u64(const void* p) {
    ulonglong2 v;
    asm volatile("ld.global.cg.v2.u64 {%0, %1}, [%2];"
                 : "=l"(v.x), "=l"(v.y) : "l"(p));
    return v;
}
__device__ __forceinline__ void stcg_v4f32(float* p, float a, float b, float c, float d) {
    asm volatile("st.global.cg.v4.f32 [%0], {%1, %2, %3, %4};"
                 :: "l"(p), "f"(a), "f"(b), "f"(c), "f"(d));
}
__device__ __forceinline__ float sigmoid_fast(float x) {
    return __fdividef(1.f, 1.f + __expf(-x));
}
__device__ __forceinline__ float tanh_fast(float x) {
    float e2 = __expf(2.f * fabsf(x));
    float r  = 1.f - __fdividef(2.f, e2 + 1.f);
    return copysignf(r, x);
}

// =====================================================================
// Kernel 1 (one-time ~30us): x[b][t][k] -> g_xt[t][kquad][b][4]
// =====================================================================
__global__ void __launch_bounds__(256) xpose(const float* __restrict__ x)
{
    extern __shared__ float xs[];   // 32 x 513
    const int t   = blockIdx.x;
    const int tid = threadIdx.x;
#pragma unroll
    for (int it = 0; it < 16; it++) {
        int b  = it * 2 + (tid >> 7);
        int k4 = (tid & 127) << 2;
        float4 v = *(const float4*)&x[((size_t)b * SS + t) * II + k4];
        xs[b * 513 + k4 + 0] = v.x;
        xs[b * 513 + k4 + 1] = v.y;
        xs[b * 513 + k4 + 2] = v.z;
        xs[b * 513 + k4 + 3] = v.w;
    }
    __syncthreads();
#pragma unroll
    for (int it = 0; it < 16; it++) {
        int idx = tid + it * 256;        // 4096 = 128 kq x 32 b
        int kq  = idx >> 5;
        int b   = idx & 31;
        float4 v = make_float4(xs[b * 513 + 4 * kq + 0], xs[b * 513 + 4 * kq + 1],
                               xs[b * 513 + 4 * kq + 2], xs[b * 513 + 4 * kq + 3]);
        *(float4*)&g_xt[((size_t)t * 128 + kq) * 128 + b * 4] = v;
    }
}

// 16 rows x 32-k (16 u64); warp-uniform W (1 wf per LDS.128); 2 acc banks
__device__ __forceinline__ void fma_chunk32(
    const float* __restrict__ Wp, const u64* __restrict__ v2,
    float* __restrict__ sums, int kb)
{
#pragma unroll
    for (int r0 = 0; r0 < 16; r0 += 4) {
        u64 a0[4], a1[4];
#pragma unroll
        for (int rr = 0; rr < 4; rr++) { a0[rr] = 0ull; a1[rr] = 0ull; }
#pragma unroll
        for (int q = 0; q < 8; q++) {
#pragma unroll
            for (int rr = 0; rr < 4; rr++) {
                ulonglong2 wv = *(const ulonglong2*)&Wp[(r0 + rr) * 512 + kb + q * 4];
                a0[rr] = fma2(wv.x, v2[2 * q + 0], a0[rr]);
                a1[rr] = fma2(wv.y, v2[2 * q + 1], a1[rr]);
            }
        }
#pragma unroll
        for (int rr = 0; rr < 4; rr++) {
            float2 f = unpack2(add2(a0[rr], a1[rr]));
            sums[r0 + rr] += f.x + f.y;
        }
    }
}

// =====================================================================
// Kernel 2: persistent LSTM, bucketed producer/consumer sync (no global
// barrier). 128 CTAs x 544 thr (17 warps). Warp 0 = reducer/publisher;
// warps 1-16 = workers, k-chunk (w-1)*32. CTA owns 4 h-idx = 1 h-quad.
// Bucket b (16 total) = CTAs 8b..8b+7 produce h-quads for k-chunk b*32.
// Worker step: x-FMA -> bucket wait -> h-FMA -> STS(part[t&1]) -> arrive.
// Reducer step: bar.sync -> reduce + nonlin + h/out stores -> publish.
// part is double-buffered: worker's t+2 overwrite of part[t&1] is chained
// behind every reducer's publish of t+2, hence own reducer's step-t read.
// =====================================================================
__global__ void __launch_bounds__(544, 1) lstm_rec(
    const float* __restrict__ Wih, const float* __restrict__ Whh,
    const float* __restrict__ bih, const float* __restrict__ bhh,
    const float* __restrict__ h0, const float* __restrict__ c0,
    float* __restrict__ out, int write_hc)
{
    extern __shared__ float sm[];
    float* Wih_s = sm;                 // 16 x 512 = 32KB
    float* Whh_s = sm + 8192;          // 32KB
    float* part0 = sm + 16384;         // [16 rows][16 workers][32 b] = 32KB
    float* part1 = sm + 24576;         // double buffer, 32KB

    const int tid  = threadIdx.x;
    const int w    = tid >> 5;         // 0 = reducer, 1..16 = workers
    const int lane = tid & 31;         // lane = batch
    const int cta  = blockIdx.x;
    const int j0   = cta * 4;          // this CTA's h-quad

    // ---- load W slices (16 rows x 512 each), rows r = type*4 + jj ----
#pragma unroll
    for (int s = 0; s < 8; s++) {
        int idx = tid + s * 544;              // 4096 float4 slots
        if (idx < 4096) {
            int mat = idx >> 11;              // 0 = Wih, 1 = Whh
            int rr  = (idx & 2047) >> 7;
            int k4  = (idx & 127) << 2;
            int g   = (rr >> 2) * 512 + j0 + (rr & 3);
            float* dst = (mat ? Whh_s : Wih_s) + rr * 512 + k4;
            const float* src = (mat ? Whh : Wih) + (size_t)g * 512 + k4;
            *(float4*)dst = *(const float4*)src;
        }
    }
    __syncthreads();

    if (w == 0) {
        // ======================= reducer warp =======================
        float4 creg = *(const float4*)&c0[(size_t)lane * HH + j0];
        float4 bias[4];
#pragma unroll
        for (int t4 = 0; t4 < 4; t4++) {
            float4 b1 = *(const float4*)&bih[t4 * 512 + j0];
            float4 b2 = *(const float4*)&bhh[t4 * 512 + j0];
            bias[t4] = make_float4(b1.x + b2.x, b1.y + b2.y, b1.z + b2.z, b1.w + b2.w);
        }
        // publish h(0): store quad, then release-add all 4 bucket copies
        {
            float4 hv = *(const float4*)&h0[(size_t)lane * HH + j0];
            stcg_v4f32(&g_hb[0][(cta * 32 + lane) * 4], hv.x, hv.y, hv.z, hv.w);
            __syncwarp();
            if (lane < 4)
                asm volatile("red.release.gpu.global.add.u32 [%0], %1;"
                             :: "l"(&g_bkt[((cta >> 3) * 4 + lane) * 32]), "r"(1u)
                             : "memory");
        }

#pragma unroll 1
        for (int t = 0; t < SS; t++) {
            asm volatile("bar.sync 1, 544;" ::: "memory");   // workers' STS done
            const float* part = (t & 1) ? part1 : part0;

            float gate[4][4];   // [type][jj]
#pragma unroll
            for (int t4 = 0; t4 < 4; t4++) {
                float bv[4] = {bias[t4].x, bias[t4].y, bias[t4].z, bias[t4].w};
#pragma unroll
                for (int jj = 0; jj < 4; jj++) {
                    int r = t4 * 4 + jj;
                    float s = bv[jj];
#pragma unroll
                    for (int ww = 0; ww < 16; ww++)
                        s += part[r * 512 + ww * 32 + lane];
                    gate[t4][jj] = s;
                }
            }
            float hv[4], cv[4];
            float cr[4] = {creg.x, creg.y, creg.z, creg.w};
#pragma unroll
            for (int jj = 0; jj < 4; jj++) {
                float ig = sigmoid_fast(gate[0][jj]);
                float fg = sigmoid_fast(gate[1][jj]);
                float gg = tanh_fast(gate[2][jj]);
                float og = sigmoid_fast(gate[3][jj]);
                float c  = fg * cr[jj] + ig * gg;
                cv[jj] = c;
                hv[jj] = og * tanh_fast(c);
            }
            creg = make_float4(cv[0], cv[1], cv[2], cv[3]);

            stcg_v4f32(&g_hb[(t + 1) & 1][(cta * 32 + lane) * 4],
                       hv[0], hv[1], hv[2], hv[3]);
            *(float4*)&out[((size_t)lane * SS + t) * HH + j0] =
                make_float4(hv[0], hv[1], hv[2], hv[3]);
            if (t == SS - 1 && write_hc) {
                size_t base = (size_t)BB * SS * HH;
                *(float4*)&out[base + (size_t)lane * HH + j0] =
                    make_float4(hv[0], hv[1], hv[2], hv[3]);
                *(float4*)&out[base + (size_t)BB * HH + (size_t)lane * HH + j0] =
                    make_float4(cv[0], cv[1], cv[2], cv[3]);
            }
            __syncwarp();
            if (t < SS - 1 && lane < 4)
                asm volatile("red.release.gpu.global.add.u32 [%0], %1;"
                             :: "l"(&g_bkt[((cta >> 3) * 4 + lane) * 32]), "r"(1u)
                             : "memory");
        }
    } else {
        // ======================= worker warps =======================
        const int kc = w - 1;            // k-chunk index 0..15 (32 k each)
        const int kb = kc * 32;
        const unsigned* ctr = &g_bkt[(kc * 4 + (cta & 3)) * 32];
        const ulonglong2* xq = (const ulonglong2*)g_xt;

#pragma unroll 1
        for (int t = 0; t < SS; t++) {
            float sums[16];
#pragma unroll
            for (int r = 0; r < 16; r++) sums[r] = 0.f;

            // ---- x phase (shadow work while producers publish h(t)) ----
            {
                u64 xv[16];
#pragma unroll
                for (int i = 0; i < 8; i++) {
                    ulonglong2 v = ldcg_v2u64(&xq[((size_t)t * 128 + kc * 8 + i) * 32 + lane]);
                    xv[2 * i + 0] = v.x;
                    xv[2 * i + 1] = v.y;
                }
                fma_chunk32(Wih_s, xv, sums, kb);
            }

            // ---- local wait: this k-chunk's 8 producers published h(t) ----
            while (ld_acq(ctr) < 8u * (unsigned)(t + 1)) { }

            // ---- h phase ----
            {
                const ulonglong2* hq = (const ulonglong2*)g_hb[t & 1];
                u64 hv[16];
#pragma unroll
                for (int i = 0; i < 8; i++) {
                    ulonglong2 v = ldcg_v2u64(&hq[(kc * 8 + i) * 32 + lane]);
                    hv[2 * i + 0] = v.x;
                    hv[2 * i + 1] = v.y;
                }
                fma_chunk32(Whh_s, hv, sums, kb);
            }

            float* part = (t & 1) ? part1 : part0;
#pragma unroll
            for (int r = 0; r < 16; r++)
                part[r * 512 + kc * 32 + lane] = sums[r];
            // non-blocking arrive; reducer's bar.sync consumes. Run-ahead
            // overwrite of part[t&1] happens at t+2, which chains behind
            // every reducer's publish of t+2 -> own reducer read part(t).
            asm volatile("bar.arrive 1, 544;" ::: "memory");
        }
    }

    // ---- cleanup: reset counters for graph replay ----
    __syncthreads();
    if (tid == 0) {
        unsigned old;
        asm volatile("atom.acq_rel.gpu.global.add.u32 %0, [%1], %2;"
                     : "=r"(old) : "l"(&g_end), "r"(1u));
        if (old == 127u) {
#pragma unroll
            for (int i = 0; i < 64; i++) g_bkt[i * 32] = 0u;
            g_end = 0u;
            __threadfence();
        }
    }
}

// =====================================================================
extern "C" void kernel_launch(void* const* d_in, const int* in_sizes, int n_in,
                              void* d_out, int out_size)
{
    const float* x   = (const float*)d_in[0];
    const float* Wih = (const float*)d_in[1];
    const float* Whh = (const float*)d_in[2];
    const float* bih = (const float*)d_in[3];
    const float* bhh = (const float*)d_in[4];
    const float* h0  = (const float*)d_in[5];
    const float* c0  = (const float*)d_in[6];
    float* out = (float*)d_out;

    long long need = (long long)BB * SS * HH + 2LL * BB * HH;
    int write_hc = ((long long)out_size >= need) ? 1 : 0;

    int xpose_smem = 32 * 513 * (int)sizeof(float);                  // ~64KB
    int rec_smem   = (32 * 512 + 2 * 16 * 512) * (int)sizeof(float); // 128KB
    cudaFuncSetAttribute(xpose, cudaFuncAttributeMaxDynamicSharedMemorySize, xpose_smem);
    cudaFuncSetAttribute(lstm_rec, cudaFuncAttributeMaxDynamicSharedMemorySize, rec_smem);

    xpose<<<SS, 256, xpose_smem>>>(x);
    lstm_rec<<<128, 544, rec_smem>>>(Wih, Whh, bih, bhh, h0, c0, out, write_hc);
}

// round 17
// speedup vs baseline: 1.3359x; 1.3359x over previous
#include <cuda_runtime.h>
#include <cuda_bf16.h>
#include <math.h>

#define BB 32
#define SS 1024
#define II 512
#define HH 512

typedef unsigned long long u64;
typedef unsigned int u32;

// ---------------- device scratch (referenced ONLY from device code!) ----------------
__device__ __nv_bfloat16 g_xhi[(size_t)BB * SS * II];   // 32MB
__device__ __nv_bfloat16 g_xlo[(size_t)BB * SS * II];   // 32MB
__device__ __nv_bfloat16 g_whi[(size_t)4 * HH * II];    // 2MB
__device__ __nv_bfloat16 g_wlo[(size_t)4 * HH * II];    // 2MB
__device__ float g_xg[(size_t)128 * SS * BB * 16];      // xg[hquad][t][b][16r], 256MB
__device__ float g_hb[2][HH * BB];                      // h ping-pong
__device__ unsigned g_bkt[8 * 4 * 32];                  // 8 buckets x 4 copies (128B apart)
__device__ unsigned g_end;

// ---------------- helpers ----------------
__device__ __forceinline__ unsigned ld_acq(const unsigned* p) {
    unsigned v;
    asm volatile("ld.acquire.gpu.u32 %0, [%1];" : "=r"(v) : "l"(p));
    return v;
}
__device__ __forceinline__ u64 fma2(u64 a, u64 b, u64 c) {
    u64 d;
    asm("fma.rn.f32x2 %0, %1, %2, %3;" : "=l"(d) : "l"(a), "l"(b), "l"(c));
    return d;
}
__device__ __forceinline__ u64 add2(u64 a, u64 b) {
    u64 d;
    asm("add.rn.f32x2 %0, %1, %2;" : "=l"(d) : "l"(a), "l"(b));
    return d;
}
__device__ __forceinline__ float2 unpack2(u64 v) {
    unsigned lo, hi;
    asm("mov.b64 {%0, %1}, %2;" : "=r"(lo), "=r"(hi) : "l"(v));
    return make_float2(__uint_as_float(lo), __uint_as_float(hi));
}
__device__ __forceinline__ ulonglong2 ldcg_v2u64(const void* p) {
    ulonglong2 v;
    asm volatile("ld.global.cg.v2.u64 {%0, %1}, [%2];"
                 : "=l"(v.x), "=l"(v.y) : "l"(p));
    return v;
}
__device__ __forceinline__ void stcg_v4f32(float* p, float a, float b, float c, float d) {
    asm volatile("st.global.cg.v4.f32 [%0], {%1, %2, %3, %4};"
                 :: "l"(p), "f"(a), "f"(b), "f"(c), "f"(d));
}
__device__ __forceinline__ float sigmoid_fast(float x) {
    return __fdividef(1.f, 1.f + __expf(-x));
}
__device__ __forceinline__ float tanh_fast(float x) {
    float e2 = __expf(2.f * fabsf(x));
    float r  = 1.f - __fdividef(2.f, e2 + 1.f);
    return copysignf(r, x);
}
// mma.sync m16n8k16 bf16 (baseline PTX, compiles at compute_103)
__device__ __forceinline__ void mma_bf16(float* c, const u32* a, const u32* b) {
    asm volatile(
        "mma.sync.aligned.m16n8k16.row.col.f32.bf16.bf16.f32 "
        "{%0,%1,%2,%3}, {%4,%5,%6,%7}, {%8,%9}, {%0,%1,%2,%3};"
        : "+f"(c[0]), "+f"(c[1]), "+f"(c[2]), "+f"(c[3])
        : "r"(a[0]), "r"(a[1]), "r"(a[2]), "r"(a[3]), "r"(b[0]), "r"(b[1]));
}

__device__ __forceinline__ void split4(const float* __restrict__ src, size_t i,
                                       __nv_bfloat16* hi, __nv_bfloat16* lo)
{
    float4 v = *(const float4*)&src[i];
    __nv_bfloat16 h0 = __float2bfloat16(v.x), h1 = __float2bfloat16(v.y);
    __nv_bfloat16 h2 = __float2bfloat16(v.z), h3 = __float2bfloat16(v.w);
    ushort4 hv = make_ushort4(__bfloat16_as_ushort(h0), __bfloat16_as_ushort(h1),
                              __bfloat16_as_ushort(h2), __bfloat16_as_ushort(h3));
    __nv_bfloat16 l0 = __float2bfloat16(v.x - __bfloat162float(h0));
    __nv_bfloat16 l1 = __float2bfloat16(v.y - __bfloat162float(h1));
    __nv_bfloat16 l2 = __float2bfloat16(v.z - __bfloat162float(h2));
    __nv_bfloat16 l3 = __float2bfloat16(v.w - __bfloat162float(h3));
    ushort4 lv = make_ushort4(__bfloat16_as_ushort(l0), __bfloat16_as_ushort(l1),
                              __bfloat16_as_ushort(l2), __bfloat16_as_ushort(l3));
    *(ushort4*)&hi[i] = hv;
    *(ushort4*)&lo[i] = lv;
}

// =====================================================================
// Kernels A1/A2: split fp32 -> bf16 hi + lo. Device globals referenced
// INSIDE device code (host-passed __device__ symbols are host shadows
// on ATS-capable GB300 -> silent garbage; R16's bug).
// =====================================================================
__global__ void __launch_bounds__(256) split_x(const float* __restrict__ x)
{
    size_t i = ((size_t)blockIdx.x * 256 + threadIdx.x) * 4;
    split4(x, i, g_xhi, g_xlo);
}
__global__ void __launch_bounds__(256) split_w(const float* __restrict__ Wih)
{
    size_t i = ((size_t)blockIdx.x * 256 + threadIdx.x) * 4;
    split4(Wih, i, g_whi, g_wlo);
}

// =====================================================================
// Kernel B: xg = x @ Wih^T via mma.sync bf16 3-term split.
// Grid (16 nblk, 256 mblk), 256 thr (8 warps, 2m x 4n of 64x32 tiles).
// =====================================================================
#define TP 40   // tile pitch (bf16)
#define A_HI 0
#define A_LO (128 * TP)
#define B_HI (2 * 128 * TP)
#define B_LO (3 * 128 * TP)
#define GEMM_SMEM (128 * 132 * 4)   // 67584B (C overlay dominates tiles 40KB)

__global__ void __launch_bounds__(256) xg_gemm()
{
    extern __shared__ char smc[];
    __nv_bfloat16* tile = (__nv_bfloat16*)smc;
    float* Csm = (float*)smc;

    const int tid = threadIdx.x;
    const int w   = tid >> 5;
    const int gid = (tid & 31) >> 2;
    const int tq  = tid & 3;
    const int wm  = w >> 2;
    const int wn  = w & 3;
    const int n0  = blockIdx.x * 128;
    const int m0  = blockIdx.y * 128;

    float acc[4][4][4];
#pragma unroll
    for (int mf = 0; mf < 4; mf++)
#pragma unroll
        for (int nf = 0; nf < 4; nf++)
#pragma unroll
            for (int i = 0; i < 4; i++) acc[mf][nf][i] = 0.f;

#pragma unroll 1
    for (int ch = 0; ch < 16; ch++) {
        const int k0 = ch * 32;
#pragma unroll
        for (int it = 0; it < 2; it++) {
            int idx = tid + it * 256;
            int row = idx >> 2, c8 = idx & 3;
            uint4 va = *(const uint4*)&g_xhi[(size_t)(m0 + row) * II + k0 + c8 * 8];
            uint4 vb = *(const uint4*)&g_xlo[(size_t)(m0 + row) * II + k0 + c8 * 8];
            uint4 vc = *(const uint4*)&g_whi[(size_t)(n0 + row) * II + k0 + c8 * 8];
            uint4 vd = *(const uint4*)&g_wlo[(size_t)(n0 + row) * II + k0 + c8 * 8];
            char* pa = (char*)&tile[A_HI + row * TP + c8 * 8];
            char* pb = (char*)&tile[A_LO + row * TP + c8 * 8];
            char* pc = (char*)&tile[B_HI + row * TP + c8 * 8];
            char* pd = (char*)&tile[B_LO + row * TP + c8 * 8];
            *(uint2*)pa = make_uint2(va.x, va.y); *(uint2*)(pa + 8) = make_uint2(va.z, va.w);
            *(uint2*)pb = make_uint2(vb.x, vb.y); *(uint2*)(pb + 8) = make_uint2(vb.z, vb.w);
            *(uint2*)pc = make_uint2(vc.x, vc.y); *(uint2*)(pc + 8) = make_uint2(vc.z, vc.w);
            *(uint2*)pd = make_uint2(vd.x, vd.y); *(uint2*)(pd + 8) = make_uint2(vd.z, vd.w);
        }
        __syncthreads();

#pragma unroll
        for (int ks = 0; ks < 32; ks += 16) {
            u32 ah[4][4], al[4][4];
#pragma unroll
            for (int mf = 0; mf < 4; mf++) {
                int rb = (wm * 64 + mf * 16 + gid) * TP + ks + tq * 2;
                ah[mf][0] = *(const u32*)&tile[A_HI + rb];
                ah[mf][1] = *(const u32*)&tile[A_HI + rb + 8 * TP];
                ah[mf][2] = *(const u32*)&tile[A_HI + rb + 8];
                ah[mf][3] = *(const u32*)&tile[A_HI + rb + 8 * TP + 8];
                al[mf][0] = *(const u32*)&tile[A_LO + rb];
                al[mf][1] = *(const u32*)&tile[A_LO + rb + 8 * TP];
                al[mf][2] = *(const u32*)&tile[A_LO + rb + 8];
                al[mf][3] = *(const u32*)&tile[A_LO + rb + 8 * TP + 8];
            }
#pragma unroll
            for (int nf = 0; nf < 4; nf++) {
                int nb = (wn * 32 + nf * 8 + gid) * TP + ks + tq * 2;
                u32 bh[2], bl[2];
                bh[0] = *(const u32*)&tile[B_HI + nb];
                bh[1] = *(const u32*)&tile[B_HI + nb + 8];
                bl[0] = *(const u32*)&tile[B_LO + nb];
                bl[1] = *(const u32*)&tile[B_LO + nb + 8];
#pragma unroll
                for (int mf = 0; mf < 4; mf++) {
                    mma_bf16(acc[mf][nf], ah[mf], bh);   // hi*hi
                    mma_bf16(acc[mf][nf], ah[mf], bl);   // hi*lo
                    mma_bf16(acc[mf][nf], al[mf], bh);   // lo*hi
                }
            }
        }
        __syncthreads();
    }

    // ---- epilogue: acc -> Csm (overlays tiles; all mma done) ----
#pragma unroll
    for (int mf = 0; mf < 4; mf++)
#pragma unroll
        for (int nf = 0; nf < 4; nf++) {
            int row0 = wm * 64 + mf * 16 + gid;
            int col0 = wn * 32 + nf * 8 + tq * 2;
            *(float2*)&Csm[row0 * 132 + col0] =
                make_float2(acc[mf][nf][0], acc[mf][nf][1]);
            *(float2*)&Csm[(row0 + 8) * 132 + col0] =
                make_float2(acc[mf][nf][2], acc[mf][nf][3]);
        }
    __syncthreads();

    // ---- store to g_xg[hquad][t][b][16] ----
    const int q     = n0 >> 9;
    const int ctaR0 = (n0 & 511) >> 2;
#pragma unroll
    for (int it = 0; it < 16; it++) {
        int slot = tid + it * 256;
        int lr = slot >> 7;
        int m  = slot & 127;
        float4 v = *(const float4*)&Csm[m * 132 + lr * 4];
        int b = (m0 + m) >> 10;
        int t = (m0 + m) & 1023;
        *(float4*)&g_xg[(((size_t)(ctaR0 + lr) * SS + t) * 32 + b) * 16 + q * 4] = v;
    }
}

// =====================================================================
// Kernel C: x-free persistent recurrence (R13 structure).
// 128 CTAs x 288 thr: warp 0 = reducer, warps 1-8 = workers (64-k chunk).
// =====================================================================
__device__ __forceinline__ void fma_chunk32(
    const float* __restrict__ Wp, const u64* __restrict__ v2,
    float* __restrict__ sums, int kb)
{
#pragma unroll
    for (int r0 = 0; r0 < 16; r0 += 4) {
        u64 a0[4], a1[4];
#pragma unroll
        for (int rr = 0; rr < 4; rr++) { a0[rr] = 0ull; a1[rr] = 0ull; }
#pragma unroll
        for (int qq = 0; qq < 8; qq++) {
#pragma unroll
            for (int rr = 0; rr < 4; rr++) {
                ulonglong2 wv = *(const ulonglong2*)&Wp[(r0 + rr) * 512 + kb + qq * 4];
                a0[rr] = fma2(wv.x, v2[2 * qq + 0], a0[rr]);
                a1[rr] = fma2(wv.y, v2[2 * qq + 1], a1[rr]);
            }
        }
#pragma unroll
        for (int rr = 0; rr < 4; rr++) {
            float2 f = unpack2(add2(a0[rr], a1[rr]));
            sums[r0 + rr] += f.x + f.y;
        }
    }
}

__global__ void __launch_bounds__(288, 1) lstm_rec(
    const float* __restrict__ Whh, const float* __restrict__ bih,
    const float* __restrict__ bhh, const float* __restrict__ h0,
    const float* __restrict__ c0, float* __restrict__ out, int write_hc)
{
    extern __shared__ float sm[];
    float* Whh_s = sm;                 // 16 x 512 = 32KB
    float* part  = sm + 8192;          // [16 rows][8 workers][32 b] = 16KB

    const int tid  = threadIdx.x;
    const int w    = tid >> 5;
    const int lane = tid & 31;
    const int cta  = blockIdx.x;
    const int j0   = cta * 4;

#pragma unroll
    for (int s = 0; s < 8; s++) {
        int idx = tid + s * 288;
        if (idx < 2048) {
            int rr = idx >> 7;
            int k4 = (idx & 127) << 2;
            int g  = (rr >> 2) * 512 + j0 + (rr & 3);
            *(float4*)&Whh_s[rr * 512 + k4] = *(const float4*)&Whh[(size_t)g * HH + k4];
        }
    }
    __syncthreads();

    if (w == 0) {
        // ======================= reducer warp =======================
        float4 creg = *(const float4*)&c0[(size_t)lane * HH + j0];
        float4 bias[4];
#pragma unroll
        for (int t4 = 0; t4 < 4; t4++) {
            float4 b1 = *(const float4*)&bih[t4 * 512 + j0];
            float4 b2 = *(const float4*)&bhh[t4 * 512 + j0];
            bias[t4] = make_float4(b1.x + b2.x, b1.y + b2.y, b1.z + b2.z, b1.w + b2.w);
        }
        {
            float4 hv = *(const float4*)&h0[(size_t)lane * HH + j0];
            stcg_v4f32(&g_hb[0][(cta * 32 + lane) * 4], hv.x, hv.y, hv.z, hv.w);
            __syncwarp();
            if (lane < 4)
                asm volatile("red.release.gpu.global.add.u32 [%0], %1;"
                             :: "l"(&g_bkt[((cta >> 4) * 4 + lane) * 32]), "r"(1u)
                             : "memory");
        }
        const float* xbase = &g_xg[((size_t)cta * SS) * 512 + (size_t)lane * 16];

#pragma unroll 1
        for (int t = 0; t < SS; t++) {
            float4 xf[4];
#pragma unroll
            for (int r4 = 0; r4 < 4; r4++)
                xf[r4] = *(const float4*)&xbase[(size_t)t * 512 + r4 * 4];

            asm volatile("bar.sync 1, 288;" ::: "memory");

            float gate[4][4];
#pragma unroll
            for (int t4 = 0; t4 < 4; t4++) {
                float bv[4] = {bias[t4].x, bias[t4].y, bias[t4].z, bias[t4].w};
                float xv[4] = {xf[t4].x, xf[t4].y, xf[t4].z, xf[t4].w};
#pragma unroll
                for (int jj = 0; jj < 4; jj++) {
                    int r = t4 * 4 + jj;
                    float s = bv[jj] + xv[jj];
#pragma unroll
                    for (int ww = 0; ww < 8; ww++)
                        s += part[r * 256 + ww * 32 + lane];
                    gate[t4][jj] = s;
                }
            }
            float hv[4], cv[4];
            float cr[4] = {creg.x, creg.y, creg.z, creg.w};
#pragma unroll
            for (int jj = 0; jj < 4; jj++) {
                float ig = sigmoid_fast(gate[0][jj]);
                float fg = sigmoid_fast(gate[1][jj]);
                float gg = tanh_fast(gate[2][jj]);
                float og = sigmoid_fast(gate[3][jj]);
                float c  = fg * cr[jj] + ig * gg;
                cv[jj] = c;
                hv[jj] = og * tanh_fast(c);
            }
            creg = make_float4(cv[0], cv[1], cv[2], cv[3]);

            stcg_v4f32(&g_hb[(t + 1) & 1][(cta * 32 + lane) * 4],
                       hv[0], hv[1], hv[2], hv[3]);
            *(float4*)&out[((size_t)lane * SS + t) * HH + j0] =
                make_float4(hv[0], hv[1], hv[2], hv[3]);
            if (t == SS - 1 && write_hc) {
                size_t base = (size_t)BB * SS * HH;
                *(float4*)&out[base + (size_t)lane * HH + j0] =
                    make_float4(hv[0], hv[1], hv[2], hv[3]);
                *(float4*)&out[base + (size_t)BB * HH + (size_t)lane * HH + j0] =
                    make_float4(cv[0], cv[1], cv[2], cv[3]);
            }
            __syncwarp();
            if (t < SS - 1 && lane < 4)
                asm volatile("red.release.gpu.global.add.u32 [%0], %1;"
                             :: "l"(&g_bkt[((cta >> 4) * 4 + lane) * 32]), "r"(1u)
                             : "memory");
        }
    } else {
        // ======================= worker warps =======================
        const int kw = w - 1;
        const int kb = kw * 64;
        const unsigned* ctr = &g_bkt[(kw * 4 + (cta & 3)) * 32];

#pragma unroll 1
        for (int t = 0; t < SS; t++) {
            while (ld_acq(ctr) < 16u * (unsigned)(t + 1)) { }

            const ulonglong2* hq = (const ulonglong2*)g_hb[t & 1];
            u64 hv[32];
#pragma unroll
            for (int i = 0; i < 16; i++) {
                ulonglong2 v = ldcg_v2u64(&hq[(kw * 16 + i) * 32 + lane]);
                hv[2 * i + 0] = v.x;
                hv[2 * i + 1] = v.y;
            }

            float sums[16];
#pragma unroll
            for (int r = 0; r < 16; r++) sums[r] = 0.f;
            fma_chunk32(Whh_s, hv,      sums, kb);
            fma_chunk32(Whh_s, hv + 16, sums, kb + 32);

#pragma unroll
            for (int r = 0; r < 16; r++)
                part[r * 256 + kw * 32 + lane] = sums[r];
            asm volatile("bar.arrive 1, 288;" ::: "memory");
        }
    }

    // ---- cleanup for graph replay ----
    __syncthreads();
    if (tid == 0) {
        unsigned old;
        asm volatile("atom.acq_rel.gpu.global.add.u32 %0, [%1], %2;"
                     : "=r"(old) : "l"(&g_end), "r"(1u));
        if (old == 127u) {
#pragma unroll
            for (int i = 0; i < 32; i++) g_bkt[i * 32] = 0u;
            g_end = 0u;
            __threadfence();
        }
    }
}

// =====================================================================
extern "C" void kernel_launch(void* const* d_in, const int* in_sizes, int n_in,
                              void* d_out, int out_size)
{
    const float* x   = (const float*)d_in[0];
    const float* Wih = (const float*)d_in[1];
    const float* Whh = (const float*)d_in[2];
    const float* bih = (const float*)d_in[3];
    const float* bhh = (const float*)d_in[4];
    const float* h0  = (const float*)d_in[5];
    const float* c0  = (const float*)d_in[6];
    float* out = (float*)d_out;

    long long need = (long long)BB * SS * HH + 2LL * BB * HH;
    int write_hc = ((long long)out_size >= need) ? 1 : 0;

    cudaFuncSetAttribute(xg_gemm, cudaFuncAttributeMaxDynamicSharedMemorySize,
                         GEMM_SMEM);
    int rec_smem = (16 * 512 + 16 * 256) * (int)sizeof(float);   // 48KB
    cudaFuncSetAttribute(lstm_rec, cudaFuncAttributeMaxDynamicSharedMemorySize, rec_smem);

    split_x<<<16384, 256>>>(x);      // 16.8M elems
    split_w<<<1024, 256>>>(Wih);     // 1.05M elems
    xg_gemm<<<dim3(16, 256), 256, GEMM_SMEM>>>();
    lstm_rec<<<128, 288, rec_smem>>>(Whh, bih, bhh, h0, c0, out, write_hc);
}